// round 1
// baseline (speedup 1.0000x reference)
#include <cuda_runtime.h>
#include <math_constants.h>

#define BATCH 2
#define SEQ   2048
#define DMODEL 1024
#define NHEAD 16
#define DEPTH 64
#define MTOT  (BATCH*SEQ)          // 4096
#define BH    (BATCH*NHEAD)        // 32

// Scratch (static device globals — allocation-free)
__device__ float g_qh[BATCH*NHEAD*SEQ*DEPTH];   // [b][h][l][d]
__device__ float g_kh[BATCH*NHEAD*SEQ*DEPTH];
__device__ float g_vh[BATCH*NHEAD*SEQ*DEPTH];
__device__ float g_attn[MTOT*DMODEL];           // [b*L + l][h*64 + d]

// ---------------------------------------------------------------------------
// Generic SGEMM: Y = X(M x K) @ W(K x N) + bias
// MODE 0: Y[m*N + n]      (linear)
// MODE 1: head-split: Y[((b*H + h)*L + l)*64 + d], b=m>>11,l=m&2047,h=n>>6,d=n&63
// Tile 128x128x8, 256 threads, 8x8 per thread.
// ---------------------------------------------------------------------------
template<int MODE>
__global__ __launch_bounds__(256)
void sgemm_kernel(const float* __restrict__ X, const float* __restrict__ W,
                  const float* __restrict__ bias, float* __restrict__ Y,
                  int Mdim, int Ndim, int Kdim)
{
    __shared__ float As[8][128];
    __shared__ float Bs[8][128];

    const int bm = blockIdx.y * 128;
    const int bn = blockIdx.x * 128;
    const int tid = threadIdx.x;
    const int tx = tid & 15;          // 0..15 -> n
    const int ty = tid >> 4;          // 0..15 -> m

    float acc[8][8];
    #pragma unroll
    for (int i = 0; i < 8; i++)
        #pragma unroll
        for (int j = 0; j < 8; j++) acc[i][j] = 0.f;

    const int arow = tid >> 1;            // 0..127
    const int acol = (tid & 1) << 2;      // 0 or 4
    const int brow = tid >> 5;            // 0..7
    const int bcol = (tid & 31) << 2;     // 0..124

    const float* Xp = X + (size_t)(bm + arow) * Kdim + acol;
    const float* Wp = W + (size_t)brow * Ndim + bn + bcol;

    for (int k0 = 0; k0 < Kdim; k0 += 8) {
        float4 av = *(const float4*)Xp;
        float4 bv = *(const float4*)Wp;
        As[acol + 0][arow] = av.x;
        As[acol + 1][arow] = av.y;
        As[acol + 2][arow] = av.z;
        As[acol + 3][arow] = av.w;
        *(float4*)&Bs[brow][bcol] = bv;
        __syncthreads();

        #pragma unroll
        for (int kk = 0; kk < 8; kk++) {
            float a[8], b[8];
            *(float4*)(a)     = *(const float4*)&As[kk][ty * 8];
            *(float4*)(a + 4) = *(const float4*)&As[kk][ty * 8 + 4];
            *(float4*)(b)     = *(const float4*)&Bs[kk][tx * 8];
            *(float4*)(b + 4) = *(const float4*)&Bs[kk][tx * 8 + 4];
            #pragma unroll
            for (int i = 0; i < 8; i++)
                #pragma unroll
                for (int j = 0; j < 8; j++)
                    acc[i][j] += a[i] * b[j];
        }
        __syncthreads();
        Xp += 8;
        Wp += (size_t)8 * Ndim;
    }

    #pragma unroll
    for (int i = 0; i < 8; i++) {
        const int m = bm + ty * 8 + i;
        #pragma unroll
        for (int j = 0; j < 8; j++) {
            const int n = bn + tx * 8 + j;
            float v = acc[i][j] + bias[n];
            if (MODE == 0) {
                Y[(size_t)m * Ndim + n] = v;
            } else {
                const int b = m >> 11, l = m & 2047;
                const int h = n >> 6,  d = n & 63;
                Y[(((size_t)(b * NHEAD + h)) * SEQ + l) * DEPTH + d] = v;
            }
        }
    }
}

// ---------------------------------------------------------------------------
// Scores: P[bh][m][n] = (Qh[bh][m][:] . Kh[bh][n][:]) / 8 + mask[b][m][n]*-1e9
// Tile 128x128, K=64 processed as 2 chunks of 32. 256 threads, 8x8/thread.
// ---------------------------------------------------------------------------
__global__ __launch_bounds__(256)
void scores_kernel(const float* __restrict__ qh, const float* __restrict__ kh,
                   const int* __restrict__ mask, float* __restrict__ P)
{
    __shared__ float Qs[32][128];
    __shared__ float Ks[32][128];

    const int bn = blockIdx.x * 128;
    const int bm = blockIdx.y * 128;
    const int bh = blockIdx.z;
    const int b  = bh >> 4;
    const int tid = threadIdx.x;
    const int tx = tid & 15;
    const int ty = tid >> 4;

    const float* qbase = qh + ((size_t)bh * SEQ + bm) * DEPTH;
    const float* kbase = kh + ((size_t)bh * SEQ + bn) * DEPTH;

    float acc[8][8];
    #pragma unroll
    for (int i = 0; i < 8; i++)
        #pragma unroll
        for (int j = 0; j < 8; j++) acc[i][j] = 0.f;

    for (int k0 = 0; k0 < DEPTH; k0 += 32) {
        // load 128x32 Q tile transposed; 1024 float4 / 256 threads = 4 each
        #pragma unroll
        for (int i = tid; i < 128 * 8; i += 256) {
            const int r = i >> 3;
            const int c4 = (i & 7) << 2;
            float4 t = *(const float4*)(qbase + (size_t)r * DEPTH + k0 + c4);
            Qs[c4 + 0][r] = t.x; Qs[c4 + 1][r] = t.y;
            Qs[c4 + 2][r] = t.z; Qs[c4 + 3][r] = t.w;
        }
        #pragma unroll
        for (int i = tid; i < 128 * 8; i += 256) {
            const int r = i >> 3;
            const int c4 = (i & 7) << 2;
            float4 t = *(const float4*)(kbase + (size_t)r * DEPTH + k0 + c4);
            Ks[c4 + 0][r] = t.x; Ks[c4 + 1][r] = t.y;
            Ks[c4 + 2][r] = t.z; Ks[c4 + 3][r] = t.w;
        }
        __syncthreads();

        #pragma unroll
        for (int kk = 0; kk < 32; kk++) {
            float a[8], c[8];
            *(float4*)(a)     = *(const float4*)&Qs[kk][ty * 8];
            *(float4*)(a + 4) = *(const float4*)&Qs[kk][ty * 8 + 4];
            *(float4*)(c)     = *(const float4*)&Ks[kk][tx * 8];
            *(float4*)(c + 4) = *(const float4*)&Ks[kk][tx * 8 + 4];
            #pragma unroll
            for (int i = 0; i < 8; i++)
                #pragma unroll
                for (int j = 0; j < 8; j++)
                    acc[i][j] += a[i] * c[j];
        }
        __syncthreads();
    }

    #pragma unroll
    for (int i = 0; i < 8; i++) {
        const int m = bm + ty * 8 + i;
        const int* mp = mask + ((size_t)b * SEQ + m) * SEQ + bn + tx * 8;
        float* pp = P + ((size_t)bh * SEQ + m) * SEQ + bn + tx * 8;
        #pragma unroll
        for (int j = 0; j < 8; j++) {
            pp[j] = acc[i][j] * 0.125f + (float)mp[j] * (-1e9f);
        }
    }
}

// ---------------------------------------------------------------------------
// Softmax in place: one block per row of 2048. 256 threads x 8 elems.
// ---------------------------------------------------------------------------
__global__ __launch_bounds__(256)
void softmax_kernel(float* __restrict__ P)
{
    float* row = P + (size_t)blockIdx.x * SEQ;
    const int tid = threadIdx.x;
    const int lane = tid & 31;
    const int warp = tid >> 5;

    float4 v0 = ((float4*)row)[tid * 2];
    float4 v1 = ((float4*)row)[tid * 2 + 1];

    float m = fmaxf(fmaxf(fmaxf(v0.x, v0.y), fmaxf(v0.z, v0.w)),
                    fmaxf(fmaxf(v1.x, v1.y), fmaxf(v1.z, v1.w)));

    __shared__ float red[8];
    #pragma unroll
    for (int o = 16; o > 0; o >>= 1) m = fmaxf(m, __shfl_xor_sync(0xffffffffu, m, o));
    if (lane == 0) red[warp] = m;
    __syncthreads();
    float rmax = red[0];
    #pragma unroll
    for (int i = 1; i < 8; i++) rmax = fmaxf(rmax, red[i]);
    __syncthreads();

    v0.x = __expf(v0.x - rmax); v0.y = __expf(v0.y - rmax);
    v0.z = __expf(v0.z - rmax); v0.w = __expf(v0.w - rmax);
    v1.x = __expf(v1.x - rmax); v1.y = __expf(v1.y - rmax);
    v1.z = __expf(v1.z - rmax); v1.w = __expf(v1.w - rmax);

    float s = (v0.x + v0.y + v0.z + v0.w) + (v1.x + v1.y + v1.z + v1.w);
    #pragma unroll
    for (int o = 16; o > 0; o >>= 1) s += __shfl_xor_sync(0xffffffffu, s, o);
    if (lane == 0) red[warp] = s;
    __syncthreads();
    float rsum = 0.f;
    #pragma unroll
    for (int i = 0; i < 8; i++) rsum += red[i];
    const float inv = 1.0f / rsum;

    v0.x *= inv; v0.y *= inv; v0.z *= inv; v0.w *= inv;
    v1.x *= inv; v1.y *= inv; v1.z *= inv; v1.w *= inv;
    ((float4*)row)[tid * 2]     = v0;
    ((float4*)row)[tid * 2 + 1] = v1;
}

// ---------------------------------------------------------------------------
// AV: attn[b*L+m][h*64+n] = sum_k P[bh][m][k] * Vh[bh][k][n]
// Tile 128(m) x 64(n) x 32(k). 256 threads, 8x4 per thread.
// ---------------------------------------------------------------------------
__global__ __launch_bounds__(256)
void av_kernel(const float* __restrict__ P, const float* __restrict__ vh,
               float* __restrict__ attn)
{
    __shared__ float Ps[32][128];
    __shared__ float Vs[32][64];

    const int bm = blockIdx.y * 128;
    const int bh = blockIdx.z;
    const int b  = bh >> 4;
    const int h  = bh & 15;
    const int tid = threadIdx.x;
    const int tx = tid & 15;   // n: tx*4
    const int ty = tid >> 4;   // m: ty*8

    const float* pbase = P + ((size_t)bh * SEQ + bm) * SEQ;
    const float* vbase = vh + (size_t)bh * SEQ * DEPTH;

    float acc[8][4];
    #pragma unroll
    for (int i = 0; i < 8; i++)
        #pragma unroll
        for (int j = 0; j < 4; j++) acc[i][j] = 0.f;

    for (int k0 = 0; k0 < SEQ; k0 += 32) {
        #pragma unroll
        for (int i = tid; i < 128 * 8; i += 256) {
            const int r = i >> 3;
            const int c4 = (i & 7) << 2;
            float4 t = *(const float4*)(pbase + (size_t)r * SEQ + k0 + c4);
            Ps[c4 + 0][r] = t.x; Ps[c4 + 1][r] = t.y;
            Ps[c4 + 2][r] = t.z; Ps[c4 + 3][r] = t.w;
        }
        #pragma unroll
        for (int i = tid; i < 512; i += 256) {
            const int r = i >> 4;
            const int c4 = (i & 15) << 2;
            *(float4*)&Vs[r][c4] =
                *(const float4*)(vbase + (size_t)(k0 + r) * DEPTH + c4);
        }
        __syncthreads();

        #pragma unroll
        for (int kk = 0; kk < 32; kk++) {
            float a[8], c[4];
            *(float4*)(a)     = *(const float4*)&Ps[kk][ty * 8];
            *(float4*)(a + 4) = *(const float4*)&Ps[kk][ty * 8 + 4];
            *(float4*)(c)     = *(const float4*)&Vs[kk][tx * 4];
            #pragma unroll
            for (int i = 0; i < 8; i++)
                #pragma unroll
                for (int j = 0; j < 4; j++)
                    acc[i][j] += a[i] * c[j];
        }
        __syncthreads();
    }

    #pragma unroll
    for (int i = 0; i < 8; i++) {
        const int m = bm + ty * 8 + i;
        float* op = attn + ((size_t)(b * SEQ + m)) * DMODEL + h * DEPTH + tx * 4;
        #pragma unroll
        for (int j = 0; j < 4; j++) op[j] = acc[i][j];
    }
}

// ---------------------------------------------------------------------------
extern "C" void kernel_launch(void* const* d_in, const int* in_sizes, int n_in,
                              void* d_out, int out_size)
{
    const float* q    = (const float*)d_in[0];
    const float* k    = (const float*)d_in[1];
    const float* v    = (const float*)d_in[2];
    const int*   mask = (const int*)  d_in[3];
    const float* Wq   = (const float*)d_in[4];
    const float* bq   = (const float*)d_in[5];
    const float* Wk   = (const float*)d_in[6];
    const float* bk   = (const float*)d_in[7];
    const float* Wv   = (const float*)d_in[8];
    const float* bv   = (const float*)d_in[9];
    const float* Wo   = (const float*)d_in[10];
    const float* bo   = (const float*)d_in[11];

    float* out   = (float*)d_out;                       // (B, L, D)
    float* attnW = out + (size_t)MTOT * DMODEL;         // (B, H, L, L)

    float *qh, *kh, *vh, *attn;
    cudaGetSymbolAddress((void**)&qh,   g_qh);
    cudaGetSymbolAddress((void**)&kh,   g_kh);
    cudaGetSymbolAddress((void**)&vh,   g_vh);
    cudaGetSymbolAddress((void**)&attn, g_attn);

    dim3 gProj(DMODEL / 128, MTOT / 128);   // (8, 32)

    sgemm_kernel<1><<<gProj, 256>>>(q, Wq, bq, qh, MTOT, DMODEL, DMODEL);
    sgemm_kernel<1><<<gProj, 256>>>(k, Wk, bk, kh, MTOT, DMODEL, DMODEL);
    sgemm_kernel<1><<<gProj, 256>>>(v, Wv, bv, vh, MTOT, DMODEL, DMODEL);

    scores_kernel<<<dim3(SEQ / 128, SEQ / 128, BH), 256>>>(qh, kh, mask, attnW);

    softmax_kernel<<<BH * SEQ, 256>>>(attnW);

    av_kernel<<<dim3(1, SEQ / 128, BH), 256>>>(attnW, vh, attn);

    sgemm_kernel<0><<<gProj, 256>>>(attn, Wo, bo, out, MTOT, DMODEL, DMODEL);
}

// round 3
// speedup vs baseline: 2.1993x; 2.1993x over previous
#include <cuda_runtime.h>
#include <cuda_bf16.h>
#include <cstdint>

#define SEQ   2048
#define DM    1024
#define NH    16
#define DEP   64
#define MTOT  4096
#define BH    32

// ---------------------------------------------------------------------------
// Device scratch (allocation-free __device__ globals)
// ---------------------------------------------------------------------------
__device__ __nv_bfloat16 g_wq_hi[DM*DM], g_wq_lo[DM*DM];
__device__ __nv_bfloat16 g_wk_hi[DM*DM], g_wk_lo[DM*DM];
__device__ __nv_bfloat16 g_wv_hi[DM*DM], g_wv_lo[DM*DM];
__device__ __nv_bfloat16 g_wo_hi[DM*DM], g_wo_lo[DM*DM];
__device__ __nv_bfloat16 g_qh_hi[BH*SEQ*DEP], g_qh_lo[BH*SEQ*DEP];
__device__ __nv_bfloat16 g_kh_hi[BH*SEQ*DEP], g_kh_lo[BH*SEQ*DEP];
__device__ __nv_bfloat16 g_vt_hi[BH*DEP*SEQ], g_vt_lo[BH*DEP*SEQ];
__device__ __nv_bfloat16 g_at_hi[MTOT*DM],    g_at_lo[MTOT*DM];

// ---------------------------------------------------------------------------
// Helpers (all plain-target-legal: cp.async sm_80, ldmatrix sm_75, mma sm_80)
// ---------------------------------------------------------------------------
__device__ __forceinline__ uint32_t smem_u32(const void* p) {
    uint32_t a;
    asm("{ .reg .u64 t; cvta.to.shared.u64 t, %1; cvt.u32.u64 %0, t; }"
        : "=r"(a) : "l"(p));
    return a;
}
#define CP16(s, g)  asm volatile("cp.async.cg.shared.global [%0], [%1], 16;" :: "r"(s), "l"(g))
#define CP_COMMIT() asm volatile("cp.async.commit_group;" ::: "memory")
#define CP_WAIT0()  asm volatile("cp.async.wait_group 0;" ::: "memory")
#define CP_WAIT1()  asm volatile("cp.async.wait_group 1;" ::: "memory")

#define LDSM4(R, addr) \
    asm volatile("ldmatrix.sync.aligned.m8n8.x4.shared.b16 {%0,%1,%2,%3}, [%4];" \
        : "=r"((R)[0]), "=r"((R)[1]), "=r"((R)[2]), "=r"((R)[3]) : "r"(addr))

#define MMA16816(d, a, b) \
    asm volatile("mma.sync.aligned.m16n8k16.row.col.f32.bf16.bf16.f32 " \
        "{%0,%1,%2,%3}, {%4,%5,%6,%7}, {%8,%9}, {%0,%1,%2,%3};" \
        : "+f"((d)[0]), "+f"((d)[1]), "+f"((d)[2]), "+f"((d)[3]) \
        : "r"((a)[0]), "r"((a)[1]), "r"((a)[2]), "r"((a)[3]), "r"((b)[0]), "r"((b)[1]))

__device__ __forceinline__ uint32_t swz(uint32_t b) { return b ^ ((b >> 3) & 0x70); }

__device__ __forceinline__ uint32_t pack_bf2(float x, float y) {
    __nv_bfloat162 t;
    t.x = __float2bfloat16(x);
    t.y = __float2bfloat16(y);
    return *(uint32_t*)&t;
}

// ---------------------------------------------------------------------------
// W[k][n] fp32 -> Wt[n][k] bf16 hi/lo
// ---------------------------------------------------------------------------
__global__ void transpose_split_kernel(const float* __restrict__ W,
                                       __nv_bfloat16* __restrict__ hi,
                                       __nv_bfloat16* __restrict__ lo)
{
    __shared__ float s[32][33];
    const int bx = blockIdx.x * 32, by = blockIdx.y * 32;
    const int tx = threadIdx.x, ty = threadIdx.y;  // 32 x 8
    #pragma unroll
    for (int j = 0; j < 4; j++)
        s[ty + j * 8][tx] = W[(size_t)(by + ty + j * 8) * DM + bx + tx];
    __syncthreads();
    #pragma unroll
    for (int j = 0; j < 4; j++) {
        int n = bx + ty + j * 8, k = by + tx;
        float v = s[tx][ty + j * 8];
        __nv_bfloat16 h = __float2bfloat16(v);
        hi[(size_t)n * DM + k] = h;
        lo[(size_t)n * DM + k] = __float2bfloat16(v - __bfloat162float(h));
    }
}

// ---------------------------------------------------------------------------
// Softmax in place (P fp32, row length 2048)
// ---------------------------------------------------------------------------
__global__ __launch_bounds__(256)
void softmax_kernel(float* __restrict__ P)
{
    float* row = P + (size_t)blockIdx.x * SEQ;
    const int tid = threadIdx.x, lane = tid & 31, warp = tid >> 5;

    float4 v0 = ((float4*)row)[tid * 2];
    float4 v1 = ((float4*)row)[tid * 2 + 1];
    float m = fmaxf(fmaxf(fmaxf(v0.x, v0.y), fmaxf(v0.z, v0.w)),
                    fmaxf(fmaxf(v1.x, v1.y), fmaxf(v1.z, v1.w)));
    __shared__ float red[8];
    #pragma unroll
    for (int o = 16; o > 0; o >>= 1) m = fmaxf(m, __shfl_xor_sync(0xffffffffu, m, o));
    if (lane == 0) red[warp] = m;
    __syncthreads();
    float rmax = red[0];
    #pragma unroll
    for (int i = 1; i < 8; i++) rmax = fmaxf(rmax, red[i]);

    float e[8];
    e[0]=__expf(v0.x-rmax); e[1]=__expf(v0.y-rmax); e[2]=__expf(v0.z-rmax); e[3]=__expf(v0.w-rmax);
    e[4]=__expf(v1.x-rmax); e[5]=__expf(v1.y-rmax); e[6]=__expf(v1.z-rmax); e[7]=__expf(v1.w-rmax);
    float s = 0.f;
    #pragma unroll
    for (int i = 0; i < 8; i++) s += e[i];
    #pragma unroll
    for (int o = 16; o > 0; o >>= 1) s += __shfl_xor_sync(0xffffffffu, s, o);
    __syncthreads();
    if (lane == 0) red[warp] = s;
    __syncthreads();
    float rsum = 0.f;
    #pragma unroll
    for (int i = 0; i < 8; i++) rsum += red[i];
    const float inv = 1.0f / rsum;

    v0.x=e[0]*inv; v0.y=e[1]*inv; v0.z=e[2]*inv; v0.w=e[3]*inv;
    v1.x=e[4]*inv; v1.y=e[5]*inv; v1.z=e[6]*inv; v1.w=e[7]*inv;
    ((float4*)row)[tid * 2]     = v0;
    ((float4*)row)[tid * 2 + 1] = v1;
}

// ---------------------------------------------------------------------------
// HMMA split-bf16 GEMM: D[m][n] = sum_k A[m,k]*B[n,k] in near-fp32 precision.
// Per 64-wide K chunk: hi/lo tiles in smem, 3 mma terms (ah*bh + ah*bl + al*bh).
// A source: fp32 (convert on the fly) or pre-split bf16 hi/lo. B: pre-split.
// CTA: 128 x NT, 256 threads, warps 2x4 (NT=128: 64x32) or 4x2 (NT=64: 32x32).
// ---------------------------------------------------------------------------
#define EPI_LIN    0
#define EPI_HEAD   1
#define EPI_VT     2
#define EPI_SCORES 3
#define EPI_AV     4

template<int NT, int EPI, bool AFP32>
__global__ void __launch_bounds__(256, 1)
mma_gemm(const float* __restrict__ Afp,
         const __nv_bfloat16* __restrict__ Ahi, const __nv_bfloat16* __restrict__ Alo,
         const __nv_bfloat16* __restrict__ Bhi, const __nv_bfloat16* __restrict__ Blo,
         const float* __restrict__ bias, const int* __restrict__ mask,
         float* __restrict__ outf, __nv_bfloat16* __restrict__ oh,
         __nv_bfloat16* __restrict__ ol,
         int Kt, size_t aStride, size_t bStride)
{
    extern __shared__ char smem[];
    const uint32_t sb = smem_u32(smem);
    const int tid = threadIdx.x, lane = tid & 31, wid = tid >> 5;
    const int bn = blockIdx.x * NT, bm = blockIdx.y * 128, z = blockIdx.z;

    // smem layout
    constexpr uint32_t STG   = 0;                          // fp32 staging: 2 x 32768
    constexpr uint32_t AOFF  = AFP32 ? 65536u : 0u;
    constexpr uint32_t ABUFS = AFP32 ? 1u : 2u;
    constexpr uint32_t ABUF  = 32768;                      // hi @ +0, lo @ +16384
    constexpr uint32_t BOFF  = AOFF + ABUFS * ABUF;
    constexpr uint32_t BBUF  = NT * 256;                   // hi @ +0, lo @ +NT*128

    constexpr int MF = (NT == 128) ? 4 : 2;
    constexpr int NF = 4;
    const int warpM = (NT == 128) ? ((wid >> 2) * 64) : ((wid >> 1) * 32);
    const int warpN = (NT == 128) ? ((wid & 3) * 32)  : ((wid & 1) * 32);

    const float* Ap = AFP32 ? (Afp + (size_t)z * aStride) : nullptr;
    const __nv_bfloat16* Ah = AFP32 ? nullptr : (Ahi + (size_t)z * aStride);
    const __nv_bfloat16* Al = AFP32 ? nullptr : (Alo + (size_t)z * aStride);
    const __nv_bfloat16* Bh = Bhi + (size_t)z * bStride;
    const __nv_bfloat16* Bl = Blo + (size_t)z * bStride;

    // precomputed swizzled ldmatrix lane offsets (per k16 step)
    uint32_t a_sw[4], b_sw[4];
    #pragma unroll
    for (int kk = 0; kk < 4; kk++) {
        a_sw[kk] = swz(((uint32_t)(lane & 15) << 7) + kk * 32 + ((uint32_t)(lane >> 4) << 4));
        b_sw[kk] = swz((((uint32_t)((lane & 7) | ((lane >> 4) << 3))) << 7)
                       + kk * 32 + (((uint32_t)(lane >> 3) & 1) << 4));
    }

    float acc[MF][NF][4];
    #pragma unroll
    for (int i = 0; i < MF; i++)
        #pragma unroll
        for (int j = 0; j < NF; j++)
            #pragma unroll
            for (int r = 0; r < 4; r++) acc[i][j][r] = 0.f;

    auto issue = [&](int c, int buf) {
        const int k0 = c << 6;
        if (AFP32) {
            #pragma unroll
            for (int i = 0; i < 8; i++) {
                int u = tid + i * 256;
                int row = u >> 4, c4 = u & 15;
                CP16(sb + STG + buf * 32768 + u * 16,
                     Ap + (size_t)(bm + row) * Kt + k0 + c4 * 4);
            }
        } else {
            #pragma unroll
            for (int i = 0; i < 4; i++) {
                int u = tid + i * 256;
                int row = u >> 3, c8 = u & 7;
                uint32_t d = swz(row * 128 + c8 * 16);
                const size_t src = (size_t)(bm + row) * Kt + k0 + c8 * 8;
                CP16(sb + AOFF + buf * ABUF + d,         Ah + src);
                CP16(sb + AOFF + buf * ABUF + 16384 + d, Al + src);
            }
        }
        #pragma unroll
        for (int i = 0; i < NT / 32; i++) {
            int u = tid + i * 256;
            int row = u >> 3, c8 = u & 7;
            uint32_t d = swz(row * 128 + c8 * 16);
            const size_t src = (size_t)(bn + row) * Kt + k0 + c8 * 8;
            CP16(sb + BOFF + buf * BBUF + d,            Bh + src);
            CP16(sb + BOFF + buf * BBUF + NT * 128 + d, Bl + src);
        }
        CP_COMMIT();
    };

    auto convert = [&](int buf) {   // staged fp32 -> Ahi/Alo smem (single A buffer)
        #pragma unroll
        for (int i = 0; i < 4; i++) {
            int u = tid + i * 256;
            int row = u >> 3, c16 = u & 7;
            const char* sp = smem + STG + buf * 32768 + row * 256 + c16 * 32;
            float4 f0 = *(const float4*)sp;
            float4 f1 = *(const float4*)(sp + 16);
            float v[8] = {f0.x, f0.y, f0.z, f0.w, f1.x, f1.y, f1.z, f1.w};
            __nv_bfloat16 hv[8], lv[8];
            #pragma unroll
            for (int j = 0; j < 8; j++) {
                hv[j] = __float2bfloat16(v[j]);
                lv[j] = __float2bfloat16(v[j] - __bfloat162float(hv[j]));
            }
            uint32_t d = swz(row * 128 + c16 * 16);
            *(uint4*)(smem + AOFF + d)         = *(uint4*)hv;
            *(uint4*)(smem + AOFF + 16384 + d) = *(uint4*)lv;
        }
    };

    auto compute = [&](int abuf, int bbuf) {
        const uint32_t AH = sb + AOFF + abuf * ABUF;
        const uint32_t ALo = AH + 16384;
        const uint32_t BB = sb + BOFF + bbuf * BBUF;
        const uint32_t BLo = BB + NT * 128;
        #pragma unroll
        for (int kk = 0; kk < 4; kk++) {
            uint32_t ah[MF][4], al[MF][4], bh[NF][2], bl[NF][2];
            #pragma unroll
            for (int mf = 0; mf < MF; mf++) {
                const uint32_t ro = (uint32_t)(warpM + mf * 16) * 128;
                LDSM4(ah[mf], AH  + ro + a_sw[kk]);
                LDSM4(al[mf], ALo + ro + a_sw[kk]);
            }
            #pragma unroll
            for (int p = 0; p < 2; p++) {
                const uint32_t ro = (uint32_t)(warpN + p * 16) * 128;
                uint32_t t[4];
                LDSM4(t, BB + ro + b_sw[kk]);
                bh[2*p][0] = t[0]; bh[2*p][1] = t[1];
                bh[2*p+1][0] = t[2]; bh[2*p+1][1] = t[3];
                LDSM4(t, BLo + ro + b_sw[kk]);
                bl[2*p][0] = t[0]; bl[2*p][1] = t[1];
                bl[2*p+1][0] = t[2]; bl[2*p+1][1] = t[3];
            }
            #pragma unroll
            for (int mf = 0; mf < MF; mf++)
                #pragma unroll
                for (int nf = 0; nf < NF; nf++) {
                    MMA16816(acc[mf][nf], ah[mf], bh[nf]);
                    MMA16816(acc[mf][nf], ah[mf], bl[nf]);
                    MMA16816(acc[mf][nf], al[mf], bh[nf]);
                }
        }
    };

    const int C = Kt >> 6;
    issue(0, 0);
    for (int c = 0; c < C; c++) {
        const int cur = c & 1;
        if (c + 1 < C) { issue(c + 1, 1 - cur); CP_WAIT1(); }
        else           { CP_WAIT0(); }
        __syncthreads();
        if (AFP32) { convert(cur); __syncthreads(); }
        compute(AFP32 ? 0 : cur, cur);
        __syncthreads();
    }

    // ---------------- epilogue: straight from registers ----------------
    const int rr = lane >> 2;          // 0..7
    const int cc = (lane & 3) * 2;     // 0,2,4,6
    #pragma unroll
    for (int mf = 0; mf < MF; mf++) {
        #pragma unroll
        for (int nf = 0; nf < NF; nf++) {
            const int n = bn + warpN + nf * 8 + cc;
            #pragma unroll
            for (int half = 0; half < 2; half++) {
                const int m = bm + warpM + mf * 16 + rr + half * 8;
                const float x = acc[mf][nf][half * 2];
                const float y = acc[mf][nf][half * 2 + 1];
                if (EPI == EPI_LIN) {
                    float2 v = { x + bias[n], y + bias[n + 1] };
                    *(float2*)(outf + (size_t)m * DM + n) = v;
                } else if (EPI == EPI_SCORES) {
                    const int2 mk = *(const int2*)(mask +
                        ((size_t)(z >> 4) * SEQ + m) * SEQ + n);
                    float2 v = { x * 0.125f + (float)mk.x * (-1e9f),
                                 y * 0.125f + (float)mk.y * (-1e9f) };
                    *(float2*)(outf + ((size_t)z * SEQ + m) * SEQ + n) = v;
                } else if (EPI == EPI_HEAD) {
                    const float vx = x + bias[n], vy = y + bias[n + 1];
                    const int b = m >> 11, l = m & 2047;
                    const int h = n >> 6, d = n & 63;
                    const size_t o = ((size_t)(b * NH + h) * SEQ + l) * DEP + d;
                    const float hx = __bfloat162float(__float2bfloat16(vx));
                    const float hy = __bfloat162float(__float2bfloat16(vy));
                    *(uint32_t*)(oh + o) = pack_bf2(vx, vy);
                    *(uint32_t*)(ol + o) = pack_bf2(vx - hx, vy - hy);
                } else if (EPI == EPI_AV) {
                    const size_t o = ((size_t)((z >> 4) * SEQ + m)) * DM
                                   + (z & 15) * DEP + n;
                    const float hx = __bfloat162float(__float2bfloat16(x));
                    const float hy = __bfloat162float(__float2bfloat16(y));
                    *(uint32_t*)(oh + o) = pack_bf2(x, y);
                    *(uint32_t*)(ol + o) = pack_bf2(x - hx, y - hy);
                } else {  // EPI_VT: transposed [bh][d][l]
                    const int b = m >> 11, l = m & 2047;
                    #pragma unroll
                    for (int j = 0; j < 2; j++) {
                        const int nn = n + j;
                        const int h = nn >> 6, d = nn & 63;
                        const float v = (j ? y : x) + bias[nn];
                        const __nv_bfloat16 hv = __float2bfloat16(v);
                        const size_t o = ((size_t)(b * NH + h) * DEP + d) * SEQ + l;
                        oh[o] = hv;
                        ol[o] = __float2bfloat16(v - __bfloat162float(hv));
                    }
                }
            }
        }
    }
}

// ---------------------------------------------------------------------------
extern "C" void kernel_launch(void* const* d_in, const int* in_sizes, int n_in,
                              void* d_out, int out_size)
{
    const float* q    = (const float*)d_in[0];
    const float* k    = (const float*)d_in[1];
    const float* v    = (const float*)d_in[2];
    const int*   mask = (const int*)  d_in[3];
    const float* Wq   = (const float*)d_in[4];
    const float* bq   = (const float*)d_in[5];
    const float* Wk   = (const float*)d_in[6];
    const float* bk   = (const float*)d_in[7];
    const float* Wv   = (const float*)d_in[8];
    const float* bv   = (const float*)d_in[9];
    const float* Wo   = (const float*)d_in[10];
    const float* bo   = (const float*)d_in[11];

    float* out   = (float*)d_out;
    float* attnW = out + (size_t)MTOT * DM;

    __nv_bfloat16 *wqh,*wql,*wkh,*wkl,*wvh,*wvl,*woh,*wol;
    __nv_bfloat16 *qhh,*qhl,*khh,*khl,*vth,*vtl,*ath,*atl;
    cudaGetSymbolAddress((void**)&wqh, g_wq_hi); cudaGetSymbolAddress((void**)&wql, g_wq_lo);
    cudaGetSymbolAddress((void**)&wkh, g_wk_hi); cudaGetSymbolAddress((void**)&wkl, g_wk_lo);
    cudaGetSymbolAddress((void**)&wvh, g_wv_hi); cudaGetSymbolAddress((void**)&wvl, g_wv_lo);
    cudaGetSymbolAddress((void**)&woh, g_wo_hi); cudaGetSymbolAddress((void**)&wol, g_wo_lo);
    cudaGetSymbolAddress((void**)&qhh, g_qh_hi); cudaGetSymbolAddress((void**)&qhl, g_qh_lo);
    cudaGetSymbolAddress((void**)&khh, g_kh_hi); cudaGetSymbolAddress((void**)&khl, g_kh_lo);
    cudaGetSymbolAddress((void**)&vth, g_vt_hi); cudaGetSymbolAddress((void**)&vtl, g_vt_lo);
    cudaGetSymbolAddress((void**)&ath, g_at_hi); cudaGetSymbolAddress((void**)&atl, g_at_lo);

    const int SM_PROJ = 65536 + 32768 + 2 * 128 * 256;  // 163840
    const int SM_SC   = 2 * 32768 + 2 * 128 * 256;      // 131072
    const int SM_AV   = 65536 + 32768 + 2 * 64 * 256;   // 131072

    cudaFuncSetAttribute(mma_gemm<128, EPI_HEAD,   true>,  cudaFuncAttributeMaxDynamicSharedMemorySize, SM_PROJ);
    cudaFuncSetAttribute(mma_gemm<128, EPI_VT,     true>,  cudaFuncAttributeMaxDynamicSharedMemorySize, SM_PROJ);
    cudaFuncSetAttribute(mma_gemm<128, EPI_SCORES, false>, cudaFuncAttributeMaxDynamicSharedMemorySize, SM_SC);
    cudaFuncSetAttribute(mma_gemm<64,  EPI_AV,     true>,  cudaFuncAttributeMaxDynamicSharedMemorySize, SM_AV);
    cudaFuncSetAttribute(mma_gemm<128, EPI_LIN,    false>, cudaFuncAttributeMaxDynamicSharedMemorySize, SM_SC);

    // 1. weight transpose + split (small)
    dim3 tb(32, 8), tg(DM / 32, DM / 32);
    transpose_split_kernel<<<tg, tb>>>(Wq, wqh, wql);
    transpose_split_kernel<<<tg, tb>>>(Wk, wkh, wkl);
    transpose_split_kernel<<<tg, tb>>>(Wv, wvh, wvl);
    transpose_split_kernel<<<tg, tb>>>(Wo, woh, wol);

    // 2. projections (fp32 A converted on the fly)
    dim3 gProj(DM / 128, MTOT / 128, 1);
    mma_gemm<128, EPI_HEAD, true><<<gProj, 256, SM_PROJ>>>(
        q, nullptr, nullptr, wqh, wql, bq, nullptr, nullptr, qhh, qhl, DM, 0, 0);
    mma_gemm<128, EPI_HEAD, true><<<gProj, 256, SM_PROJ>>>(
        k, nullptr, nullptr, wkh, wkl, bk, nullptr, nullptr, khh, khl, DM, 0, 0);
    mma_gemm<128, EPI_VT, true><<<gProj, 256, SM_PROJ>>>(
        v, nullptr, nullptr, wvh, wvl, bv, nullptr, nullptr, vth, vtl, DM, 0, 0);

    // 3. scores with fused scale + mask -> attnW fp32
    mma_gemm<128, EPI_SCORES, false><<<dim3(SEQ / 128, SEQ / 128, BH), 256, SM_SC>>>(
        nullptr, qhh, qhl, khh, khl, nullptr, mask, attnW, nullptr, nullptr,
        DEP, (size_t)SEQ * DEP, (size_t)SEQ * DEP);

    // 4. softmax in place
    softmax_kernel<<<BH * SEQ, 256>>>(attnW);

    // 5. AV (P fp32 converted on the fly) -> at hi/lo
    mma_gemm<64, EPI_AV, true><<<dim3(1, SEQ / 128, BH), 256, SM_AV>>>(
        attnW, nullptr, nullptr, vth, vtl, nullptr, nullptr, nullptr, ath, atl,
        SEQ, (size_t)SEQ * SEQ, (size_t)DEP * SEQ);

    // 6. output projection
    mma_gemm<128, EPI_LIN, false><<<gProj, 256, SM_SC>>>(
        nullptr, ath, atl, woh, wol, bo, nullptr, out, nullptr, nullptr, DM, 0, 0);
}

// round 4
// speedup vs baseline: 2.5923x; 1.1787x over previous
#include <cuda_runtime.h>
#include <cuda_bf16.h>
#include <cstdint>

#define SEQ   2048
#define DM    1024
#define NH    16
#define DEP   64
#define MTOT  4096
#define BH    32

// ---------------------------------------------------------------------------
// Device scratch (allocation-free)
// ---------------------------------------------------------------------------
__device__ __nv_bfloat16 g_wq_hi[DM*DM], g_wq_lo[DM*DM];
__device__ __nv_bfloat16 g_wk_hi[DM*DM], g_wk_lo[DM*DM];
__device__ __nv_bfloat16 g_wv_hi[DM*DM], g_wv_lo[DM*DM];
__device__ __nv_bfloat16 g_wo_hi[DM*DM], g_wo_lo[DM*DM];
__device__ __nv_bfloat16 g_qh_hi[BH*SEQ*DEP], g_qh_lo[BH*SEQ*DEP];
__device__ __nv_bfloat16 g_kh_hi[BH*SEQ*DEP], g_kh_lo[BH*SEQ*DEP];
__device__ __nv_bfloat16 g_vt_hi[BH*DEP*SEQ], g_vt_lo[BH*DEP*SEQ];
__device__ __nv_bfloat16 g_at_hi[MTOT*DM],    g_at_lo[MTOT*DM];
__device__ float g_pmax[BH*16*SEQ], g_psum[BH*16*SEQ];
__device__ float g_M[BH*SEQ], g_invZ[BH*SEQ];

// ---------------------------------------------------------------------------
// Helpers
// ---------------------------------------------------------------------------
__device__ __forceinline__ uint32_t smem_u32(const void* p) {
    uint32_t a;
    asm("{ .reg .u64 t; cvta.to.shared.u64 t, %1; cvt.u32.u64 %0, t; }"
        : "=r"(a) : "l"(p));
    return a;
}
#define CP16(s, g)  asm volatile("cp.async.cg.shared.global [%0], [%1], 16;" :: "r"(s), "l"(g))
#define CP_COMMIT() asm volatile("cp.async.commit_group;" ::: "memory")
#define CP_WAIT(n)  asm volatile("cp.async.wait_group %0;" :: "n"(n) : "memory")

#define LDSM4(R, addr) \
    asm volatile("ldmatrix.sync.aligned.m8n8.x4.shared.b16 {%0,%1,%2,%3}, [%4];" \
        : "=r"((R)[0]), "=r"((R)[1]), "=r"((R)[2]), "=r"((R)[3]) : "r"(addr))

#define MMA16816(d, a, b) \
    asm volatile("mma.sync.aligned.m16n8k16.row.col.f32.bf16.bf16.f32 " \
        "{%0,%1,%2,%3}, {%4,%5,%6,%7}, {%8,%9}, {%0,%1,%2,%3};" \
        : "+f"((d)[0]), "+f"((d)[1]), "+f"((d)[2]), "+f"((d)[3]) \
        : "r"((a)[0]), "r"((a)[1]), "r"((a)[2]), "r"((a)[3]), "r"((b)[0]), "r"((b)[1]))

__device__ __forceinline__ uint32_t swz(uint32_t b) { return b ^ ((b >> 3) & 0x70); }

__device__ __forceinline__ uint32_t pack_bf2(float x, float y) {
    __nv_bfloat162 t;
    t.x = __float2bfloat16(x);
    t.y = __float2bfloat16(y);
    return *(uint32_t*)&t;
}

__device__ __forceinline__ void lane_sw(int lane, uint32_t* a_sw, uint32_t* b_sw) {
    #pragma unroll
    for (int kk = 0; kk < 4; kk++) {
        a_sw[kk] = swz(((uint32_t)(lane & 15) << 7) + kk * 32 + ((uint32_t)(lane >> 4) << 4));
        b_sw[kk] = swz((((uint32_t)((lane & 7) | ((lane >> 4) << 3))) << 7)
                       + kk * 32 + (((uint32_t)(lane >> 3) & 1) << 4));
    }
}

// 64-wide K chunk, 3-term split-bf16 MMA
template<int MF, int NF>
__device__ __forceinline__ void compute_chunk(
    uint32_t AH, uint32_t AL, uint32_t BHb, uint32_t BLb,
    int warpM, int warpN, const uint32_t* a_sw, const uint32_t* b_sw,
    float (*acc)[NF][4])
{
    #pragma unroll
    for (int kk = 0; kk < 4; kk++) {
        uint32_t ah[MF][4], al[MF][4], bh[NF][2], bl[NF][2];
        #pragma unroll
        for (int mf = 0; mf < MF; mf++) {
            const uint32_t ro = (uint32_t)(warpM + mf * 16) * 128;
            LDSM4(ah[mf], AH + ro + a_sw[kk]);
            LDSM4(al[mf], AL + ro + a_sw[kk]);
        }
        #pragma unroll
        for (int p = 0; p < NF / 2; p++) {
            const uint32_t ro = (uint32_t)(warpN + p * 16) * 128;
            uint32_t t[4];
            LDSM4(t, BHb + ro + b_sw[kk]);
            bh[2*p][0] = t[0]; bh[2*p][1] = t[1];
            bh[2*p+1][0] = t[2]; bh[2*p+1][1] = t[3];
            LDSM4(t, BLb + ro + b_sw[kk]);
            bl[2*p][0] = t[0]; bl[2*p][1] = t[1];
            bl[2*p+1][0] = t[2]; bl[2*p+1][1] = t[3];
        }
        #pragma unroll
        for (int mf = 0; mf < MF; mf++)
            #pragma unroll
            for (int nf = 0; nf < NF; nf++) {
                MMA16816(acc[mf][nf], ah[mf], bh[nf]);
                MMA16816(acc[mf][nf], ah[mf], bl[nf]);
                MMA16816(acc[mf][nf], al[mf], bh[nf]);
            }
    }
}

// ---------------------------------------------------------------------------
// W[k][n] fp32 -> Wt[n][k] bf16 hi/lo; 4 matrices via z
// ---------------------------------------------------------------------------
__global__ void transpose_split_kernel(
    const float* W0, const float* W1, const float* W2, const float* W3,
    __nv_bfloat16* h0, __nv_bfloat16* h1, __nv_bfloat16* h2, __nv_bfloat16* h3,
    __nv_bfloat16* l0, __nv_bfloat16* l1, __nv_bfloat16* l2, __nv_bfloat16* l3)
{
    const float* Ws[4] = {W0, W1, W2, W3};
    __nv_bfloat16* hs[4] = {h0, h1, h2, h3};
    __nv_bfloat16* ls[4] = {l0, l1, l2, l3};
    const int z = blockIdx.z;
    const float* W = Ws[z];
    __nv_bfloat16* hi = hs[z];
    __nv_bfloat16* lo = ls[z];

    __shared__ float s[32][33];
    const int bx = blockIdx.x * 32, by = blockIdx.y * 32;
    const int tx = threadIdx.x, ty = threadIdx.y;  // 32 x 8
    #pragma unroll
    for (int j = 0; j < 4; j++)
        s[ty + j * 8][tx] = W[(size_t)(by + ty + j * 8) * DM + bx + tx];
    __syncthreads();
    #pragma unroll
    for (int j = 0; j < 4; j++) {
        int n = bx + ty + j * 8, k = by + tx;
        float v = s[tx][ty + j * 8];
        __nv_bfloat16 h = __float2bfloat16(v);
        hi[(size_t)n * DM + k] = h;
        lo[(size_t)n * DM + k] = __float2bfloat16(v - __bfloat162float(h));
    }
}

// ---------------------------------------------------------------------------
// Projections: A fp32 (q/k/v selected by z), B pre-split. CTA 128x128.
// ---------------------------------------------------------------------------
__global__ void __launch_bounds__(256, 1)
gemm_proj(const float* __restrict__ qp, const float* __restrict__ kp,
          const float* __restrict__ vp,
          const __nv_bfloat16* __restrict__ wqh, const __nv_bfloat16* __restrict__ wkh,
          const __nv_bfloat16* __restrict__ wvh,
          const __nv_bfloat16* __restrict__ wql, const __nv_bfloat16* __restrict__ wkl,
          const __nv_bfloat16* __restrict__ wvl,
          const float* __restrict__ bqp, const float* __restrict__ bkp,
          const float* __restrict__ bvp,
          __nv_bfloat16* __restrict__ qhh, __nv_bfloat16* __restrict__ khh,
          __nv_bfloat16* __restrict__ vth,
          __nv_bfloat16* __restrict__ qhl, __nv_bfloat16* __restrict__ khl,
          __nv_bfloat16* __restrict__ vtl)
{
    extern __shared__ char smem[];
    const uint32_t sb = smem_u32(smem);
    const int tid = threadIdx.x, lane = tid & 31, wid = tid >> 5;
    const int bn = blockIdx.x * 128, bm = blockIdx.y * 128, z = blockIdx.z;

    const float* Aps[3] = {qp, kp, vp};
    const __nv_bfloat16* Bhs[3] = {wqh, wkh, wvh};
    const __nv_bfloat16* Bls[3] = {wql, wkl, wvl};
    const float* bias_s[3] = {bqp, bkp, bvp};
    __nv_bfloat16* ohs[3] = {qhh, khh, vth};
    __nv_bfloat16* ols[3] = {qhl, khl, vtl};
    const float* Ap = Aps[z];
    const __nv_bfloat16* Bh = Bhs[z];
    const __nv_bfloat16* Bl = Bls[z];
    const float* bias = bias_s[z];
    __nv_bfloat16* oh = ohs[z];
    __nv_bfloat16* ol = ols[z];

    constexpr uint32_t AOFF = 0, ABUF = 32768;           // hi@0 lo@16384, x2 bufs
    constexpr uint32_t BOFF = 65536, BBUF = 32768;       // hi@0 lo@16384, x3 bufs
    const int warpM = (wid >> 2) * 64, warpN = (wid & 3) * 32;

    uint32_t a_sw[4], b_sw[4];
    lane_sw(lane, a_sw, b_sw);

    float acc[4][4][4];
    #pragma unroll
    for (int i = 0; i < 4; i++)
        #pragma unroll
        for (int j = 0; j < 4; j++)
            #pragma unroll
            for (int r = 0; r < 4; r++) acc[i][j][r] = 0.f;

    float4 sv[8];
    auto ldgA = [&](int c) {
        const int k0 = c << 6;
        #pragma unroll
        for (int j = 0; j < 8; j++) {
            int g = j * 256 + tid, row = g >> 4, c4 = g & 15;
            sv[j] = *(const float4*)(Ap + (size_t)(bm + row) * DM + k0 + c4 * 4);
        }
    };
    auto convA = [&](int buf) {
        #pragma unroll
        for (int j = 0; j < 8; j++) {
            int g = j * 256 + tid, row = g >> 4, c4 = g & 15;
            float vv[4] = {sv[j].x, sv[j].y, sv[j].z, sv[j].w};
            float h[4];
            #pragma unroll
            for (int t = 0; t < 4; t++) h[t] = __bfloat162float(__float2bfloat16(vv[t]));
            uint2 H = { pack_bf2(vv[0], vv[1]), pack_bf2(vv[2], vv[3]) };
            uint2 L = { pack_bf2(vv[0]-h[0], vv[1]-h[1]), pack_bf2(vv[2]-h[2], vv[3]-h[3]) };
            uint32_t d = swz((uint32_t)row * 128 + c4 * 8);
            *(uint2*)(smem + AOFF + buf * ABUF + d)         = H;
            *(uint2*)(smem + AOFF + buf * ABUF + 16384 + d) = L;
        }
    };
    auto issueB = [&](int c, int buf) {
        const int k0 = c << 6;
        #pragma unroll
        for (int i = 0; i < 4; i++) {
            int u = tid + i * 256, row = u >> 3, c8 = u & 7;
            uint32_t d = swz((uint32_t)row * 128 + c8 * 16);
            const size_t src = (size_t)(bn + row) * DM + k0 + c8 * 8;
            CP16(sb + BOFF + buf * BBUF + d,         Bh + src);
            CP16(sb + BOFF + buf * BBUF + 16384 + d, Bl + src);
        }
        CP_COMMIT();
    };

    const int C = DM >> 6;  // 16
    ldgA(0);
    issueB(0, 0);
    issueB(1, 1);
    convA(0);
    ldgA(1);
    for (int c = 0; c < C; c++) {
        if (c + 1 < C) CP_WAIT(1); else CP_WAIT(0);
        __syncthreads();
        if (c + 2 < C) issueB(c + 2, (c + 2) % 3);
        compute_chunk<4, 4>(sb + AOFF + (c & 1) * ABUF,
                            sb + AOFF + (c & 1) * ABUF + 16384,
                            sb + BOFF + (c % 3) * BBUF,
                            sb + BOFF + (c % 3) * BBUF + 16384,
                            warpM, warpN, a_sw, b_sw, acc);
        if (c + 1 < C) {
            convA((c + 1) & 1);
            if (c + 2 < C) ldgA(c + 2);
        }
    }

    // epilogue
    const int rr = lane >> 2, cc = (lane & 3) * 2;
    #pragma unroll
    for (int mf = 0; mf < 4; mf++)
        #pragma unroll
        for (int nf = 0; nf < 4; nf++) {
            const int n = bn + warpN + nf * 8 + cc;
            #pragma unroll
            for (int half = 0; half < 2; half++) {
                const int m = bm + warpM + mf * 16 + rr + half * 8;
                const float x = acc[mf][nf][half*2]     + bias[n];
                const float y = acc[mf][nf][half*2 + 1] + bias[n + 1];
                const int b = m >> 11, l = m & 2047;
                if (z < 2) {  // head layout [bh][l][d]
                    const int h = n >> 6, d = n & 63;
                    const size_t o = ((size_t)(b * NH + h) * SEQ + l) * DEP + d;
                    const float hx = __bfloat162float(__float2bfloat16(x));
                    const float hy = __bfloat162float(__float2bfloat16(y));
                    *(uint32_t*)(oh + o) = pack_bf2(x, y);
                    *(uint32_t*)(ol + o) = pack_bf2(x - hx, y - hy);
                } else {      // V transposed [bh][d][l]
                    #pragma unroll
                    for (int j = 0; j < 2; j++) {
                        const int nn = n + j;
                        const int h = nn >> 6, d = nn & 63;
                        const float v = j ? y : x;
                        const __nv_bfloat16 hv = __float2bfloat16(v);
                        const size_t o = ((size_t)(b * NH + h) * DEP + d) * SEQ + l;
                        oh[o] = hv;
                        ol[o] = __float2bfloat16(v - __bfloat162float(hv));
                    }
                }
            }
        }
}

// ---------------------------------------------------------------------------
// Scores: pre-split A,B (K=64), fused scale+mask, write S fp32 + softmax partials
// ---------------------------------------------------------------------------
__global__ void __launch_bounds__(256, 1)
gemm_scores(const __nv_bfloat16* __restrict__ Ahi, const __nv_bfloat16* __restrict__ Alo,
            const __nv_bfloat16* __restrict__ Bhi, const __nv_bfloat16* __restrict__ Blo,
            const int* __restrict__ mask, float* __restrict__ S,
            float* __restrict__ pmax, float* __restrict__ psum)
{
    extern __shared__ char smem[];
    const uint32_t sb = smem_u32(smem);
    const int tid = threadIdx.x, lane = tid & 31, wid = tid >> 5;
    const int bn = blockIdx.x * 128, bm = blockIdx.y * 128, z = blockIdx.z;

    const __nv_bfloat16* Ah = Ahi + (size_t)z * SEQ * DEP;
    const __nv_bfloat16* Al = Alo + (size_t)z * SEQ * DEP;
    const __nv_bfloat16* Bh = Bhi + (size_t)z * SEQ * DEP;
    const __nv_bfloat16* Bl = Blo + (size_t)z * SEQ * DEP;

    const int warpM = (wid >> 2) * 64, warpN = (wid & 3) * 32;
    uint32_t a_sw[4], b_sw[4];
    lane_sw(lane, a_sw, b_sw);

    // load A(128x64 hi/lo) @0/16384, B @32768/49152
    #pragma unroll
    for (int i = 0; i < 4; i++) {
        int u = tid + i * 256, row = u >> 3, c8 = u & 7;
        uint32_t d = swz((uint32_t)row * 128 + c8 * 16);
        const size_t sa = (size_t)(bm + row) * DEP + c8 * 8;
        const size_t sbo = (size_t)(bn + row) * DEP + c8 * 8;
        CP16(sb + d,         Ah + sa);
        CP16(sb + 16384 + d, Al + sa);
        CP16(sb + 32768 + d, Bh + sbo);
        CP16(sb + 49152 + d, Bl + sbo);
    }
    CP_COMMIT();
    CP_WAIT(0);
    __syncthreads();

    float acc[4][4][4];
    #pragma unroll
    for (int i = 0; i < 4; i++)
        #pragma unroll
        for (int j = 0; j < 4; j++)
            #pragma unroll
            for (int r = 0; r < 4; r++) acc[i][j][r] = 0.f;

    compute_chunk<4, 4>(sb, sb + 16384, sb + 32768, sb + 49152,
                        warpM, warpN, a_sw, b_sw, acc);

    // epilogue: scale + mask, write S, accumulate partials
    const int rr = lane >> 2, cc = (lane & 3) * 2;
    #pragma unroll
    for (int mf = 0; mf < 4; mf++)
        #pragma unroll
        for (int half = 0; half < 2; half++) {
            const int m = bm + warpM + mf * 16 + rr + half * 8;
            #pragma unroll
            for (int nf = 0; nf < 4; nf++) {
                const int n = bn + warpN + nf * 8 + cc;
                const int2 mk = *(const int2*)(mask + ((size_t)(z >> 4) * SEQ + m) * SEQ + n);
                float x = acc[mf][nf][half*2]     * 0.125f + (float)mk.x * (-1e9f);
                float y = acc[mf][nf][half*2 + 1] * 0.125f + (float)mk.y * (-1e9f);
                acc[mf][nf][half*2] = x; acc[mf][nf][half*2+1] = y;
                float2 v = {x, y};
                *(float2*)(S + ((size_t)z * SEQ + m) * SEQ + n) = v;
            }
        }

    // per-(row, warp-slice) max & expsum
    float* smax = (float*)(smem + 65536);   // [4][128]
    float* ssum = smax + 512;
    #pragma unroll
    for (int mf = 0; mf < 4; mf++)
        #pragma unroll
        for (int half = 0; half < 2; half++) {
            float mx = -3.4e38f;
            #pragma unroll
            for (int nf = 0; nf < 4; nf++) {
                mx = fmaxf(mx, acc[mf][nf][half*2]);
                mx = fmaxf(mx, acc[mf][nf][half*2+1]);
            }
            mx = fmaxf(mx, __shfl_xor_sync(0xffffffffu, mx, 1));
            mx = fmaxf(mx, __shfl_xor_sync(0xffffffffu, mx, 2));
            float sm = 0.f;
            #pragma unroll
            for (int nf = 0; nf < 4; nf++) {
                sm += __expf(acc[mf][nf][half*2]   - mx);
                sm += __expf(acc[mf][nf][half*2+1] - mx);
            }
            sm += __shfl_xor_sync(0xffffffffu, sm, 1);
            sm += __shfl_xor_sync(0xffffffffu, sm, 2);
            if ((lane & 3) == 0) {
                const int r = warpM + mf * 16 + rr + half * 8;
                smax[(wid & 3) * 128 + r] = mx;
                ssum[(wid & 3) * 128 + r] = sm;
            }
        }
    __syncthreads();
    if (tid < 128) {
        float M = smax[tid];
        M = fmaxf(M, smax[128 + tid]);
        M = fmaxf(M, smax[256 + tid]);
        M = fmaxf(M, smax[384 + tid]);
        float Zp = 0.f;
        #pragma unroll
        for (int w = 0; w < 4; w++)
            Zp += ssum[w * 128 + tid] * __expf(smax[w * 128 + tid] - M);
        const size_t o = ((size_t)z * 16 + blockIdx.x) * SEQ + bm + tid;
        pmax[o] = M;
        psum[o] = Zp;
    }
}

// ---------------------------------------------------------------------------
// Combine partials -> row max M and invZ
// ---------------------------------------------------------------------------
__global__ void __launch_bounds__(256)
combine_kernel(const float* __restrict__ pmax, const float* __restrict__ psum,
               float* __restrict__ gM, float* __restrict__ gInvZ)
{
    const int R = blockIdx.x * 256 + threadIdx.x;   // 0..65535
    const int bh = R >> 11, m = R & 2047;
    float mx[16];
    float M = -3.4e38f;
    #pragma unroll
    for (int t = 0; t < 16; t++) {
        mx[t] = pmax[((size_t)bh * 16 + t) * SEQ + m];
        M = fmaxf(M, mx[t]);
    }
    float Z = 0.f;
    #pragma unroll
    for (int t = 0; t < 16; t++)
        Z += psum[((size_t)bh * 16 + t) * SEQ + m] * __expf(mx[t] - M);
    gM[R] = M;
    gInvZ[R] = 1.0f / Z;
}

// ---------------------------------------------------------------------------
// AV: A = raw S fp32 -> softmax finalize (w = exp(s-M)*invZ), write w in place,
// split to hi/lo for 3-term MMA against pre-split V^T. CTA 128x64.
// ---------------------------------------------------------------------------
__global__ void __launch_bounds__(256, 1)
gemm_av(float* __restrict__ S,
        const __nv_bfloat16* __restrict__ Bhi, const __nv_bfloat16* __restrict__ Blo,
        const float* __restrict__ gM, const float* __restrict__ gInvZ,
        __nv_bfloat16* __restrict__ oh, __nv_bfloat16* __restrict__ ol)
{
    extern __shared__ char smem[];
    const uint32_t sb = smem_u32(smem);
    const int tid = threadIdx.x, lane = tid & 31, wid = tid >> 5;
    const int bm = blockIdx.y * 128, z = blockIdx.z;

    float* Sp = S + (size_t)z * SEQ * SEQ;
    const __nv_bfloat16* Bh = Bhi + (size_t)z * DEP * SEQ;
    const __nv_bfloat16* Bl = Blo + (size_t)z * DEP * SEQ;
    const int Rbase = z * SEQ + bm;

    constexpr uint32_t AOFF = 0, ABUF = 32768;      // hi@0 lo@16384, x2
    constexpr uint32_t BOFF = 65536, BBUF = 16384;  // hi@0 lo@8192, x3
    const int warpM = (wid >> 1) * 32, warpN = (wid & 1) * 32;

    uint32_t a_sw[4], b_sw[4];
    lane_sw(lane, a_sw, b_sw);

    float acc[2][4][4];
    #pragma unroll
    for (int i = 0; i < 2; i++)
        #pragma unroll
        for (int j = 0; j < 4; j++)
            #pragma unroll
            for (int r = 0; r < 4; r++) acc[i][j][r] = 0.f;

    float4 sv[8];
    auto ldgA = [&](int c) {
        const int k0 = c << 6;
        #pragma unroll
        for (int j = 0; j < 8; j++) {
            int g = j * 256 + tid, row = g >> 4, c4 = g & 15;
            sv[j] = *(const float4*)(Sp + (size_t)(bm + row) * SEQ + k0 + c4 * 4);
        }
    };
    auto convA = [&](int c, int buf) {
        const int k0 = c << 6;
        #pragma unroll
        for (int j = 0; j < 8; j++) {
            int g = j * 256 + tid, row = g >> 4, c4 = g & 15;
            const float M = gM[Rbase + row], iZ = gInvZ[Rbase + row];
            float vv[4];
            vv[0] = __expf(sv[j].x - M) * iZ;
            vv[1] = __expf(sv[j].y - M) * iZ;
            vv[2] = __expf(sv[j].z - M) * iZ;
            vv[3] = __expf(sv[j].w - M) * iZ;
            *(float4*)(Sp + (size_t)(bm + row) * SEQ + k0 + c4 * 4) =
                make_float4(vv[0], vv[1], vv[2], vv[3]);
            float h[4];
            #pragma unroll
            for (int t = 0; t < 4; t++) h[t] = __bfloat162float(__float2bfloat16(vv[t]));
            uint2 H = { pack_bf2(vv[0], vv[1]), pack_bf2(vv[2], vv[3]) };
            uint2 L = { pack_bf2(vv[0]-h[0], vv[1]-h[1]), pack_bf2(vv[2]-h[2], vv[3]-h[3]) };
            uint32_t d = swz((uint32_t)row * 128 + c4 * 8);
            *(uint2*)(smem + AOFF + buf * ABUF + d)         = H;
            *(uint2*)(smem + AOFF + buf * ABUF + 16384 + d) = L;
        }
    };
    auto issueB = [&](int c, int buf) {
        const int k0 = c << 6;
        #pragma unroll
        for (int i = 0; i < 2; i++) {
            int u = tid + i * 256, row = u >> 3, c8 = u & 7;
            uint32_t d = swz((uint32_t)row * 128 + c8 * 16);
            const size_t src = (size_t)row * SEQ + k0 + c8 * 8;
            CP16(sb + BOFF + buf * BBUF + d,        Bh + src);
            CP16(sb + BOFF + buf * BBUF + 8192 + d, Bl + src);
        }
        CP_COMMIT();
    };

    const int C = SEQ >> 6;  // 32
    ldgA(0);
    issueB(0, 0);
    issueB(1, 1);
    convA(0, 0);
    ldgA(1);
    for (int c = 0; c < C; c++) {
        if (c + 1 < C) CP_WAIT(1); else CP_WAIT(0);
        __syncthreads();
        if (c + 2 < C) issueB(c + 2, (c + 2) % 3);
        compute_chunk<2, 4>(sb + AOFF + (c & 1) * ABUF,
                            sb + AOFF + (c & 1) * ABUF + 16384,
                            sb + BOFF + (c % 3) * BBUF,
                            sb + BOFF + (c % 3) * BBUF + 8192,
                            warpM, warpN, a_sw, b_sw, acc);
        if (c + 1 < C) {
            convA(c + 1, (c + 1) & 1);
            if (c + 2 < C) ldgA(c + 2);
        }
    }

    // epilogue -> at hi/lo [b*SEQ+m][h*DEP+n]
    const int rr = lane >> 2, cc = (lane & 3) * 2;
    #pragma unroll
    for (int mf = 0; mf < 2; mf++)
        #pragma unroll
        for (int nf = 0; nf < 4; nf++) {
            const int n = warpN + nf * 8 + cc;
            #pragma unroll
            for (int half = 0; half < 2; half++) {
                const int m = bm + warpM + mf * 16 + rr + half * 8;
                const float x = acc[mf][nf][half*2];
                const float y = acc[mf][nf][half*2+1];
                const size_t o = ((size_t)((z >> 4) * SEQ + m)) * DM + (z & 15) * DEP + n;
                const float hx = __bfloat162float(__float2bfloat16(x));
                const float hy = __bfloat162float(__float2bfloat16(y));
                *(uint32_t*)(oh + o) = pack_bf2(x, y);
                *(uint32_t*)(ol + o) = pack_bf2(x - hx, y - hy);
            }
        }
}

// ---------------------------------------------------------------------------
// Output projection: pre-split A (at) and B (Wo), fp32 out + bias. CTA 128x128.
// ---------------------------------------------------------------------------
__global__ void __launch_bounds__(256, 1)
gemm_out(const __nv_bfloat16* __restrict__ Ahi, const __nv_bfloat16* __restrict__ Alo,
         const __nv_bfloat16* __restrict__ Bhi, const __nv_bfloat16* __restrict__ Blo,
         const float* __restrict__ bias, float* __restrict__ outf)
{
    extern __shared__ char smem[];
    const uint32_t sb = smem_u32(smem);
    const int tid = threadIdx.x, lane = tid & 31, wid = tid >> 5;
    const int bn = blockIdx.x * 128, bm = blockIdx.y * 128;

    constexpr uint32_t AOFF = 0, ABUF = 32768;      // x3 bufs
    constexpr uint32_t BOFF = 98304, BBUF = 32768;  // x3 bufs
    const int warpM = (wid >> 2) * 64, warpN = (wid & 3) * 32;

    uint32_t a_sw[4], b_sw[4];
    lane_sw(lane, a_sw, b_sw);

    float acc[4][4][4];
    #pragma unroll
    for (int i = 0; i < 4; i++)
        #pragma unroll
        for (int j = 0; j < 4; j++)
            #pragma unroll
            for (int r = 0; r < 4; r++) acc[i][j][r] = 0.f;

    auto issueAB = [&](int c, int buf) {
        const int k0 = c << 6;
        #pragma unroll
        for (int i = 0; i < 4; i++) {
            int u = tid + i * 256, row = u >> 3, c8 = u & 7;
            uint32_t d = swz((uint32_t)row * 128 + c8 * 16);
            const size_t sa = (size_t)(bm + row) * DM + k0 + c8 * 8;
            const size_t sbo = (size_t)(bn + row) * DM + k0 + c8 * 8;
            CP16(sb + AOFF + buf * ABUF + d,         Ahi + sa);
            CP16(sb + AOFF + buf * ABUF + 16384 + d, Alo + sa);
            CP16(sb + BOFF + buf * BBUF + d,         Bhi + sbo);
            CP16(sb + BOFF + buf * BBUF + 16384 + d, Blo + sbo);
        }
        CP_COMMIT();
    };

    const int C = DM >> 6;  // 16
    issueAB(0, 0);
    issueAB(1, 1);
    for (int c = 0; c < C; c++) {
        if (c + 1 < C) CP_WAIT(1); else CP_WAIT(0);
        __syncthreads();
        if (c + 2 < C) issueAB(c + 2, (c + 2) % 3);
        compute_chunk<4, 4>(sb + AOFF + (c % 3) * ABUF,
                            sb + AOFF + (c % 3) * ABUF + 16384,
                            sb + BOFF + (c % 3) * BBUF,
                            sb + BOFF + (c % 3) * BBUF + 16384,
                            warpM, warpN, a_sw, b_sw, acc);
    }

    const int rr = lane >> 2, cc = (lane & 3) * 2;
    #pragma unroll
    for (int mf = 0; mf < 4; mf++)
        #pragma unroll
        for (int nf = 0; nf < 4; nf++) {
            const int n = bn + warpN + nf * 8 + cc;
            #pragma unroll
            for (int half = 0; half < 2; half++) {
                const int m = bm + warpM + mf * 16 + rr + half * 8;
                float2 v = { acc[mf][nf][half*2] + bias[n],
                             acc[mf][nf][half*2+1] + bias[n+1] };
                *(float2*)(outf + (size_t)m * DM + n) = v;
            }
        }
}

// ---------------------------------------------------------------------------
extern "C" void kernel_launch(void* const* d_in, const int* in_sizes, int n_in,
                              void* d_out, int out_size)
{
    const float* q    = (const float*)d_in[0];
    const float* k    = (const float*)d_in[1];
    const float* v    = (const float*)d_in[2];
    const int*   mask = (const int*)  d_in[3];
    const float* Wq   = (const float*)d_in[4];
    const float* bq   = (const float*)d_in[5];
    const float* Wk   = (const float*)d_in[6];
    const float* bk   = (const float*)d_in[7];
    const float* Wv   = (const float*)d_in[8];
    const float* bv   = (const float*)d_in[9];
    const float* Wo   = (const float*)d_in[10];
    const float* bo   = (const float*)d_in[11];

    float* out   = (float*)d_out;
    float* attnW = out + (size_t)MTOT * DM;

    __nv_bfloat16 *wqh,*wql,*wkh,*wkl,*wvh,*wvl,*woh,*wol;
    __nv_bfloat16 *qhh,*qhl,*khh,*khl,*vth,*vtl,*ath,*atl;
    float *pmax,*psum,*gM,*gZ;
    cudaGetSymbolAddress((void**)&wqh, g_wq_hi); cudaGetSymbolAddress((void**)&wql, g_wq_lo);
    cudaGetSymbolAddress((void**)&wkh, g_wk_hi); cudaGetSymbolAddress((void**)&wkl, g_wk_lo);
    cudaGetSymbolAddress((void**)&wvh, g_wv_hi); cudaGetSymbolAddress((void**)&wvl, g_wv_lo);
    cudaGetSymbolAddress((void**)&woh, g_wo_hi); cudaGetSymbolAddress((void**)&wol, g_wo_lo);
    cudaGetSymbolAddress((void**)&qhh, g_qh_hi); cudaGetSymbolAddress((void**)&qhl, g_qh_lo);
    cudaGetSymbolAddress((void**)&khh, g_kh_hi); cudaGetSymbolAddress((void**)&khl, g_kh_lo);
    cudaGetSymbolAddress((void**)&vth, g_vt_hi); cudaGetSymbolAddress((void**)&vtl, g_vt_lo);
    cudaGetSymbolAddress((void**)&ath, g_at_hi); cudaGetSymbolAddress((void**)&atl, g_at_lo);
    cudaGetSymbolAddress((void**)&pmax, g_pmax); cudaGetSymbolAddress((void**)&psum, g_psum);
    cudaGetSymbolAddress((void**)&gM, g_M);      cudaGetSymbolAddress((void**)&gZ, g_invZ);

    const int SM_PROJ = 65536 + 3 * 32768;   // 163840
    const int SM_SC   = 65536 + 4096;        // 69632
    const int SM_AV   = 65536 + 3 * 16384;   // 114688
    const int SM_OUT  = 6 * 32768;           // 196608
    cudaFuncSetAttribute(gemm_proj,   cudaFuncAttributeMaxDynamicSharedMemorySize, SM_PROJ);
    cudaFuncSetAttribute(gemm_scores, cudaFuncAttributeMaxDynamicSharedMemorySize, SM_SC);
    cudaFuncSetAttribute(gemm_av,     cudaFuncAttributeMaxDynamicSharedMemorySize, SM_AV);
    cudaFuncSetAttribute(gemm_out,    cudaFuncAttributeMaxDynamicSharedMemorySize, SM_OUT);

    // 1. weight transposes + splits (one launch)
    transpose_split_kernel<<<dim3(32, 32, 4), dim3(32, 8)>>>(
        Wq, Wk, Wv, Wo, wqh, wkh, wvh, woh, wql, wkl, wvl, wol);

    // 2. Q/K/V projections (one launch, z selects)
    gemm_proj<<<dim3(8, 32, 3), 256, SM_PROJ>>>(
        q, k, v, wqh, wkh, wvh, wql, wkl, wvl, bq, bk, bv,
        qhh, khh, vth, qhl, khl, vtl);

    // 3. scores + mask + softmax partials (raw S into attnW region)
    gemm_scores<<<dim3(16, 16, BH), 256, SM_SC>>>(
        qhh, qhl, khh, khl, mask, attnW, pmax, psum);

    // 4. combine partials -> per-row M, invZ
    combine_kernel<<<BH * SEQ / 256, 256>>>(pmax, psum, gM, gZ);

    // 5. AV with fused softmax finalize (writes weights in place)
    gemm_av<<<dim3(1, 16, BH), 256, SM_AV>>>(
        attnW, vth, vtl, gM, gZ, ath, atl);

    // 6. output projection
    gemm_out<<<dim3(8, 32, 1), 256, SM_OUT>>>(ath, atl, woh, wol, bo, out);
}